// round 16
// baseline (speedup 1.0000x reference)
#include <cuda_runtime.h>
#include <cuda_fp16.h>
#include <cstdint>

#define HID    1024
#define INPD   512
#define BATCH  128
#define TSTEPS 256
#define G4H    4096
#define NB     128      // lstm persistent blocks
#define LT     128      // lstm threads (4 warps, all compute)

// ---- device-global scratch (no allocations allowed) ----
__device__ float    g_XS[134217728];          // [t][gate*1024+j][b] fp32 (512 MB)
__device__ uint32_t g_XTh[8388608];           // x fp16 B-frag image (32 MB)
__device__ uint32_t g_WXh[1048576];           // Wx fp16 A-frag image (4 MB)
__device__ uint32_t g_Hp[4][65536];           // h ring (4 deep), fp16 B-frag-permuted
__device__ unsigned g_flags[NB];              // flag[p] = steps completed by block p

// fp16 m16n8k16, fp32 accum
__device__ __forceinline__ void mma16(float* d, uint32_t a0, uint32_t a1, uint32_t a2,
                                      uint32_t a3, uint32_t b0, uint32_t b1) {
    asm volatile(
        "mma.sync.aligned.m16n8k16.row.col.f32.f16.f16.f32 "
        "{%0,%1,%2,%3}, {%4,%5,%6,%7}, {%8,%9}, {%0,%1,%2,%3};"
        : "+f"(d[0]), "+f"(d[1]), "+f"(d[2]), "+f"(d[3])
        : "r"(a0), "r"(a1), "r"(a2), "r"(a3), "r"(b0), "r"(b1));
}
__device__ __forceinline__ const float* sel4(const float* a, const float* b,
                                             const float* c, const float* d, int g) {
    return g == 0 ? a : (g == 1 ? b : (g == 2 ? c : d));
}
__device__ __forceinline__ float sigm(float x) { return 1.0f / (1.0f + expf(-x)); }
__device__ __forceinline__ uint32_t h2pack(float lo, float hi) {
    __half2 v = __floats2half2_rn(lo, hi);
    return *(uint32_t*)&v;
}
__device__ __forceinline__ void cp16(uint32_t dst, const void* src) {
    asm volatile("cp.async.cg.shared.global [%0], [%1], 16;" :: "r"(dst), "l"(src));
}
__device__ __forceinline__ void cpcommit() { asm volatile("cp.async.commit_group;"); }
template<int N> __device__ __forceinline__ void cpwait() {
    asm volatile("cp.async.wait_group %0;" :: "n"(N));
}
__device__ __forceinline__ unsigned ld_acq(const unsigned* p) {
    unsigned v;
    asm volatile("ld.acquire.gpu.global.u32 %0, [%1];" : "=r"(v) : "l"(p) : "memory");
    return v;
}
__device__ __forceinline__ void st_rel(unsigned* p, unsigned v) {
    asm volatile("st.release.gpu.global.u32 [%0], %1;" :: "l"(p), "r"(v) : "memory");
}

// ============================================================================
// prep_w: Wx concat -> fp16 A-frag image. Resets the flag array.
// ============================================================================
__global__ void prep_w_kernel(const float* __restrict__ Wg, const float* __restrict__ Wi,
                              const float* __restrict__ Wf, const float* __restrict__ Wo) {
    if (blockIdx.x == 0 && threadIdx.x < NB) g_flags[threadIdx.x] = 0u;
    int base = blockIdx.x * 256 + threadIdx.x;
#pragma unroll
    for (int i = 0; i < 4; ++i) {
        int o   = base + i * 262144;
        int q   = o & 3, ln = (o >> 2) & 31, k16 = (o >> 7) & 31, mt = o >> 12;
        int R   = mt * 16 + (ln >> 2) + (q & 1) * 8;
        int k   = k16 * 16 + (ln & 3) * 2 + (q >> 1) * 8;
        const float* W = sel4(Wg, Wi, Wf, Wo, R >> 10);
        const float* wr = W + (size_t)(R & 1023) * INPD + k;
        g_WXh[o] = h2pack(wr[0], wr[1]);
    }
}

// ============================================================================
// prep_h0: h0 fp32 [j][b] -> g_Hp[3] fp16 frag-permuted (read by step t=0)
// ============================================================================
__global__ void prep_h0_kernel(const float* __restrict__ h0) {
    int o = blockIdx.x * 256 + threadIdx.x;          // 65536 u32
    int reg = o & 1, lane = (o >> 1) & 31, n8 = (o >> 6) & 15, k16 = o >> 10;
    int p = lane & 3, gn = lane >> 2;
    int j = k16 * 16 + reg * 8 + 2 * p, b = n8 * 8 + gn;
    g_Hp[3][o] = h2pack(h0[j * BATCH + b], h0[(j + 1) * BATCH + b]);
}

// ============================================================================
// prep_xt: x -> fp16 B-frag image
// ============================================================================
__global__ void prep_xt_kernel(const float* __restrict__ x) {
    int o = blockIdx.x * 1024 + threadIdx.x;
#pragma unroll
    for (int i = 0; i < 4; ++i, o += 256) {
        int reg = o & 1, ln = (o >> 1) & 31, n8 = (o >> 6) & 15, k16 = (o >> 10) & 31, t = o >> 15;
        int p = ln & 3, gn = ln >> 2;
        int ii = k16 * 16 + reg * 8 + 2 * p, b = n8 * 8 + gn;
        const float* xr = x + (size_t)b * (TSTEPS * INPD) + (size_t)t * INPD + ii;
        g_XTh[o] = h2pack(xr[0], xr[1]);
    }
}

// ============================================================================
// xproj (fp16 m16n8k16, unchanged): XS[t][R][b] = Wx[R]·x[b][t] + bias[R]
// ============================================================================
__global__ void __launch_bounds__(256, 2) xproj_kernel(
    const float* __restrict__ bg, const float* __restrict__ bi,
    const float* __restrict__ bf, const float* __restrict__ bo) {
    extern __shared__ uint32_t sm[];
    const uint32_t smem0 = (uint32_t)__cvta_generic_to_shared(sm);
    const int tid = threadIdx.x;
    const int m_base = blockIdx.x * 128;
    const int mt0 = m_base >> 4;
    const int t = blockIdx.y;
    const int warp = tid >> 5, lane = tid & 31;
    const int wm = warp & 1, wn = warp >> 1;
    const int gid = lane >> 2, tig = lane & 3;

    float acc[4][4][4];
#pragma unroll
    for (int a = 0; a < 4; ++a)
#pragma unroll
        for (int b = 0; b < 4; ++b) {
            acc[a][b][0] = acc[a][b][1] = acc[a][b][2] = acc[a][b][3] = 0.f;
        }

    auto issue = [&](int kc, int buf) {
#pragma unroll
        for (int c = 0; c < 4; ++c) {                       // A: 4096 u32
            int u = c * 256 + tid;
            int idx = u >> 5, lq = u & 31;
            int k16l = idx >> 3, mtl = idx & 7;
            const uint32_t* src = g_WXh + ((size_t)(mt0 + mtl) * 32 + kc * 4 + k16l) * 128 + lq * 4;
            cp16(smem0 + (uint32_t)(buf * 4096 + idx * 128 + lq * 4) * 4, src);
        }
#pragma unroll
        for (int c = 0; c < 4; ++c) {                       // B: 4096 u32
            int u = c * 256 + tid;
            int idx = u >> 4, q16 = u & 15;
            const uint32_t* src = g_XTh + ((size_t)(t * 32 + kc * 4) * 16 + idx) * 64 + q16 * 4;
            cp16(smem0 + (uint32_t)(8192 + buf * 4096 + idx * 64 + q16 * 4) * 4, src);
        }
    };
    issue(0, 0); cpcommit();
    issue(1, 1); cpcommit();

#pragma unroll 1
    for (int kc = 0; kc < 8; ++kc) {
        if (kc < 7) cpwait<1>(); else cpwait<0>();
        __syncthreads();
        const uint32_t* A = sm + (kc & 1) * 4096;
        const uint32_t* B = sm + 8192 + (kc & 1) * 4096;
#pragma unroll
        for (int k16l = 0; k16l < 4; ++k16l) {
            uint4 af[4];
#pragma unroll
            for (int mf = 0; mf < 4; ++mf)
                af[mf] = *(const uint4*)(A + ((k16l * 8 + wm * 4 + mf) * 32 + lane) * 4);
#pragma unroll
            for (int nf = 0; nf < 4; ++nf) {
                int n8 = wn * 4 + nf;
                uint2 b01 = *(const uint2*)(B + (k16l * 16 + n8) * 64 + lane * 2);
#pragma unroll
                for (int mf = 0; mf < 4; ++mf)
                    mma16(acc[mf][nf], af[mf].x, af[mf].y, af[mf].z, af[mf].w, b01.x, b01.y);
            }
        }
        __syncthreads();
        if (kc + 2 < 8) { issue(kc + 2, kc & 1); cpcommit(); }
    }

#pragma unroll
    for (int mf = 0; mf < 4; ++mf) {
        int R0 = m_base + wm * 64 + mf * 16 + gid;
        int R1 = R0 + 8;
        float bv0 = sel4(bg, bi, bf, bo, R0 >> 10)[R0 & 1023];
        float bv1 = sel4(bg, bi, bf, bo, R1 >> 10)[R1 & 1023];
#pragma unroll
        for (int nf = 0; nf < 4; ++nf) {
            int cc = wn * 32 + nf * 8 + tig * 2;
            float2 v0 = { acc[mf][nf][0] + bv0, acc[mf][nf][1] + bv0 };
            float2 v1 = { acc[mf][nf][2] + bv1, acc[mf][nf][3] + bv1 };
            *(float2*)&g_XS[((size_t)t * G4H + R0) * BATCH + cc] = v0;
            *(float2*)&g_XS[((size_t)t * G4H + R1) * BATCH + cc] = v1;
        }
    }
}

// ============================================================================
// lstm v9: DATAFLOW sync (no global barrier). 128 blocks, 128 threads.
// M=32 (4 gates x 8 units) x N=128 x K=1024, fp16 m16n8k16.
//   - chunk c (k-rows 32c..32c+31) of h is produced by blocks 4c..4c+3 only:
//     each warp's issueB(c) polls those 4 flags (ld.acquire) then cp.asyncs.
//   - h ring 4 deep: h(t) -> g_Hp[t&3]; step t reads g_Hp[(t+3)&3].
//   - producer guard before writing h(t): all flags >= t-2 (lagged; ~free).
//   - register-resident gate epilogue; h written directly to fp16 frag image.
// smem: sW 65536 B + sB 4 x 8192 B = 98304 B.
// ============================================================================
#define SB_OFF   16384                  // u32 offset of sB

__global__ void __launch_bounds__(LT, 1) lstm_kernel(
    const float* __restrict__ c0,
    const float* __restrict__ Wg, const float* __restrict__ Wi,
    const float* __restrict__ Wf, const float* __restrict__ Wo,
    float* __restrict__ out) {
    extern __shared__ uint32_t sm[];
    uint32_t* sW  = sm;                          // 16384 u32 (fp16 A frags)
    const uint32_t smem0 = (uint32_t)__cvta_generic_to_shared(sm);
    const int tid = threadIdx.x;
    const int j0 = blockIdx.x * 8;
    const int warp = tid >> 5, lane = tid & 31;
    const int gid = lane >> 2, tig = lane & 3;
    const int hreg = (j0 >> 3) & 1;
    const int hk16 = j0 >> 4;

    // prologue: Wh -> fp16 A-frag-permuted smem (16384 u32)
#pragma unroll 1
    for (int i = 0; i < 128; ++i) {
        int o    = i * LT + tid;
        int q    = o & 3, ln = (o >> 2) & 31, mt = (o >> 7) & 1, k16 = o >> 8;
        int row  = mt * 16 + (ln >> 2) + (q & 1) * 8;
        int kk   = k16 * 16 + (ln & 3) * 2 + (q >> 1) * 8;
        const float* W = sel4(Wg, Wi, Wf, Wo, row >> 3);
        const float* wr = W + (size_t)(j0 + (row & 7)) * HID + kk;
        sW[o] = h2pack(wr[0], wr[1]);
    }
    // c state in acc layout: creg[nf*2+c] = c(u=gid, n=warp*32+nf*8+tig*2+c)
    float creg[8];
#pragma unroll
    for (int nf = 0; nf < 4; ++nf)
#pragma unroll
        for (int c = 0; c < 2; ++c)
            creg[nf * 2 + c] = c0[(j0 + gid) * BATCH + warp * 32 + nf * 8 + tig * 2 + c];
    __syncthreads();

#pragma unroll 1
    for (int t = 0; t < TSTEPS; ++t) {
        // XS prefetch into registers (no dependence on other blocks)
        float xsv[4][8];
        {
            const size_t xb = (size_t)t * (G4H * BATCH);
            const int nb = warp * 32 + tig * 2;
#pragma unroll
            for (int g = 0; g < 4; ++g) {
                const float* p = &g_XS[xb + (size_t)((g << 10) + j0 + gid) * BATCH + nb];
#pragma unroll
                for (int nf = 0; nf < 4; ++nf) {
                    xsv[g][nf * 2]     = p[nf * 8];
                    xsv[g][nf * 2 + 1] = p[nf * 8 + 1];
                }
            }
        }

        const uint32_t* hin = g_Hp[(t + 3) & 3];     // = h(t-1)
        // warp-private: wait for chunk c's 4 producer blocks, then cp.async
        auto issueB = [&](int c, int buf) {
            if (t > 0) {
                const unsigned tgt = (unsigned)t;
                for (;;) {
                    unsigned v = (lane < 4) ? ld_acq(&g_flags[4 * c + lane]) : tgt;
                    if (__all_sync(0xffffffffu, v >= tgt)) break;
                    __nanosleep(20);
                }
            }
#pragma unroll
            for (int i = 0; i < 4; ++i) {
                int rl = i * 2 + (lane >> 4);             // 0..7 = k16l*4 + r
                int col = (lane & 15) * 4;
                int k16l = rl >> 2, r = rl & 3;
                int rowg = (c * 2 + k16l) * 16 + warp * 4 + r;
                int rows = (k16l * 16 + warp * 4 + r);
                cp16(smem0 + (uint32_t)(SB_OFF + buf * 2048 + rows * 64 + col) * 4,
                     hin + (size_t)rowg * 64 + col);
            }
            cpcommit();
        };
        issueB(0, 0); issueB(1, 1); issueB(2, 2);

        float acc[2][4][4];
#pragma unroll
        for (int mt = 0; mt < 2; ++mt)
#pragma unroll
            for (int nf = 0; nf < 4; ++nf) {
                acc[mt][nf][0] = acc[mt][nf][1] = acc[mt][nf][2] = acc[mt][nf][3] = 0.f;
            }
#pragma unroll 1
        for (int kc = 0; kc < 32; ++kc) {
            cpwait<2>();                                  // warp-local wait
            const uint32_t* B = sm + SB_OFF + (kc & 3) * 2048;
#pragma unroll
            for (int k16l = 0; k16l < 2; ++k16l) {
                const int k16 = kc * 2 + k16l;
                uint4 a0 = *(const uint4*)(sW + ((k16 * 2) * 32 + lane) * 4);
                uint4 a1 = *(const uint4*)(sW + ((k16 * 2 + 1) * 32 + lane) * 4);
#pragma unroll
                for (int nf = 0; nf < 4; ++nf) {
                    const int n8 = warp * 4 + nf;
                    uint2 b01 = *(const uint2*)(B + (k16l * 16 + n8) * 64 + lane * 2);
                    mma16(acc[0][nf], a0.x, a0.y, a0.z, a0.w, b01.x, b01.y);
                    mma16(acc[1][nf], a1.x, a1.y, a1.z, a1.w, b01.x, b01.y);
                }
            }
            if (kc + 3 < 32) issueB(kc + 3, (kc + 3) & 3);
            else cpcommit();                              // keep group count exact
        }
        // register epilogue
        float hv[8];
#pragma unroll
        for (int nf = 0; nf < 4; ++nf)
#pragma unroll
            for (int c = 0; c < 2; ++c) {
                int e = nf * 2 + c;
                float zg = acc[0][nf][c]     + xsv[0][e];
                float zi = acc[0][nf][2 + c] + xsv[1][e];
                float zf = acc[1][nf][c]     + xsv[2][e];
                float zo = acc[1][nf][2 + c] + xsv[3][e];
                float cv = tanhf(zg) * sigm(zi) + creg[e] * sigm(zf);
                creg[e] = cv;
                hv[e] = tanhf(cv) * sigm(zo);
            }
        // producer guard: ring slot g_Hp[t&3] may be read (as h(t-4)) by blocks
        // still in step t-3; require all flags >= t-2 before overwriting.
        if (t >= 2 && warp == 0) {
            const unsigned tgt = (unsigned)(t - 2);
            const volatile unsigned* f = (const volatile unsigned*)g_flags;
            for (;;) {
                unsigned v0 = f[lane], v1 = f[lane + 32], v2 = f[lane + 64], v3 = f[lane + 96];
                bool ok = (v0 >= tgt) && (v1 >= tgt) && (v2 >= tgt) && (v3 >= tgt);
                if (__all_sync(0xffffffffu, ok)) break;
                __nanosleep(32);
            }
        }
        __syncthreads();
        // write h slice into ring + out
        {
            uint32_t* hw = g_Hp[t & 3];
            const int p2 = gid >> 1;
            const bool even = (gid & 1) == 0;
#pragma unroll
            for (int nf = 0; nf < 4; ++nf)
#pragma unroll
                for (int c = 0; c < 2; ++c) {
                    int e = nf * 2 + c;
                    float partner = __shfl_xor_sync(0xffffffffu, hv[e], 4);
                    if (even) {
                        uint32_t v = h2pack(hv[e], partner);
                        hw[(hk16 * 16 + warp * 4 + nf) * 64 +
                           ((tig * 2 + c) * 4 + p2) * 2 + hreg] = v;
                    }
                }
            if (t == TSTEPS - 1) {
#pragma unroll
                for (int nf = 0; nf < 4; ++nf)
#pragma unroll
                    for (int c = 0; c < 2; ++c)
                        out[(j0 + gid) * BATCH + warp * 32 + nf * 8 + tig * 2 + c] = hv[nf * 2 + c];
            }
        }
        __threadfence();                                  // release h writes
        __syncthreads();
        if (tid == 0) st_rel(&g_flags[blockIdx.x], (unsigned)(t + 1));
    }
}

// ============================================================================
extern "C" void kernel_launch(void* const* d_in, const int* in_sizes, int n_in,
                              void* d_out, int out_size) {
    const float* x   = (const float*)d_in[0];
    const float* c0  = (const float*)d_in[1];
    const float* h0  = (const float*)d_in[2];
    const float* Wgx = (const float*)d_in[3];
    const float* Wix = (const float*)d_in[4];
    const float* Wfx = (const float*)d_in[5];
    const float* Wox = (const float*)d_in[6];
    const float* Wgh = (const float*)d_in[7];
    const float* Wih = (const float*)d_in[8];
    const float* Wfh = (const float*)d_in[9];
    const float* Woh = (const float*)d_in[10];
    const float* bg  = (const float*)d_in[11];
    const float* bi  = (const float*)d_in[12];
    const float* bf  = (const float*)d_in[13];
    const float* bo  = (const float*)d_in[14];
    float* out = (float*)d_out;

    cudaFuncSetAttribute(xproj_kernel, cudaFuncAttributeMaxDynamicSharedMemorySize, 65536);
    cudaFuncSetAttribute(lstm_kernel,  cudaFuncAttributeMaxDynamicSharedMemorySize, 98304);

    prep_w_kernel<<<1024, 256>>>(Wgx, Wix, Wfx, Wox);
    prep_h0_kernel<<<256, 256>>>(h0);
    prep_xt_kernel<<<8192, 256>>>(x);
    xproj_kernel<<<dim3(32, 256), 256, 65536>>>(bg, bi, bf, bo);
    lstm_kernel<<<NB, LT, 98304>>>(c0, Wgh, Wih, Wfh, Woh, out);
}

// round 17
// speedup vs baseline: 1.7672x; 1.7672x over previous
#include <cuda_runtime.h>
#include <cuda_fp16.h>
#include <cstdint>

#define HID    1024
#define INPD   512
#define BATCH  128
#define TSTEPS 256
#define G4H    4096
#define NB     128      // lstm persistent blocks
#define LT     128      // lstm threads (4 warps, all compute)

// ---- device-global scratch (no allocations allowed) ----
__device__ float    g_XS[134217728];          // [t][gate*1024+j][b] fp32 (512 MB)
__device__ uint32_t g_XTh[8388608];           // x fp16 B-frag image (32 MB)
__device__ uint32_t g_WXh[1048576];           // Wx fp16 A-frag image (4 MB)
__device__ uint32_t g_Hp[2][65536];           // h ping-pong, fp16 B-frag-permuted
__device__ unsigned g_flags[NB];              // per-block step flags (grid barrier)

// fp16 m16n8k16, fp32 accum
__device__ __forceinline__ void mma16(float* d, uint32_t a0, uint32_t a1, uint32_t a2,
                                      uint32_t a3, uint32_t b0, uint32_t b1) {
    asm volatile(
        "mma.sync.aligned.m16n8k16.row.col.f32.f16.f16.f32 "
        "{%0,%1,%2,%3}, {%4,%5,%6,%7}, {%8,%9}, {%0,%1,%2,%3};"
        : "+f"(d[0]), "+f"(d[1]), "+f"(d[2]), "+f"(d[3])
        : "r"(a0), "r"(a1), "r"(a2), "r"(a3), "r"(b0), "r"(b1));
}
__device__ __forceinline__ const float* sel4(const float* a, const float* b,
                                             const float* c, const float* d, int g) {
    return g == 0 ? a : (g == 1 ? b : (g == 2 ? c : d));
}
__device__ __forceinline__ float sigm(float x) { return 1.0f / (1.0f + expf(-x)); }
__device__ __forceinline__ uint32_t h2pack(float lo, float hi) {
    __half2 v = __floats2half2_rn(lo, hi);
    return *(uint32_t*)&v;
}
__device__ __forceinline__ void cp16(uint32_t dst, const void* src) {
    asm volatile("cp.async.cg.shared.global [%0], [%1], 16;" :: "r"(dst), "l"(src));
}
__device__ __forceinline__ void cpcommit() { asm volatile("cp.async.commit_group;"); }
template<int N> __device__ __forceinline__ void cpwait() {
    asm volatile("cp.async.wait_group %0;" :: "n"(N));
}

// ============================================================================
// prep_w: Wx concat -> fp16 A-frag image. Resets the flag barrier.
// ============================================================================
__global__ void prep_w_kernel(const float* __restrict__ Wg, const float* __restrict__ Wi,
                              const float* __restrict__ Wf, const float* __restrict__ Wo) {
    if (blockIdx.x == 0 && threadIdx.x < NB) g_flags[threadIdx.x] = 0u;
    int base = blockIdx.x * 256 + threadIdx.x;
#pragma unroll
    for (int i = 0; i < 4; ++i) {
        int o   = base + i * 262144;
        int q   = o & 3, ln = (o >> 2) & 31, k16 = (o >> 7) & 31, mt = o >> 12;
        int R   = mt * 16 + (ln >> 2) + (q & 1) * 8;
        int k   = k16 * 16 + (ln & 3) * 2 + (q >> 1) * 8;
        const float* W = sel4(Wg, Wi, Wf, Wo, R >> 10);
        const float* wr = W + (size_t)(R & 1023) * INPD + k;
        g_WXh[o] = h2pack(wr[0], wr[1]);
    }
}

// ============================================================================
// prep_h0: h0 fp32 [j][b] -> g_Hp[1] fp16 frag-permuted
// ============================================================================
__global__ void prep_h0_kernel(const float* __restrict__ h0) {
    int o = blockIdx.x * 256 + threadIdx.x;          // 65536 u32
    int reg = o & 1, lane = (o >> 1) & 31, n8 = (o >> 6) & 15, k16 = o >> 10;
    int p = lane & 3, gn = lane >> 2;
    int j = k16 * 16 + reg * 8 + 2 * p, b = n8 * 8 + gn;
    g_Hp[1][o] = h2pack(h0[j * BATCH + b], h0[(j + 1) * BATCH + b]);
}

// ============================================================================
// prep_xt: x -> fp16 B-frag image
// ============================================================================
__global__ void prep_xt_kernel(const float* __restrict__ x) {
    int o = blockIdx.x * 1024 + threadIdx.x;
#pragma unroll
    for (int i = 0; i < 4; ++i, o += 256) {
        int reg = o & 1, ln = (o >> 1) & 31, n8 = (o >> 6) & 15, k16 = (o >> 10) & 31, t = o >> 15;
        int p = ln & 3, gn = ln >> 2;
        int ii = k16 * 16 + reg * 8 + 2 * p, b = n8 * 8 + gn;
        const float* xr = x + (size_t)b * (TSTEPS * INPD) + (size_t)t * INPD + ii;
        g_XTh[o] = h2pack(xr[0], xr[1]);
    }
}

// ============================================================================
// xproj (fp16 m16n8k16, unchanged): XS[t][R][b] = Wx[R]·x[b][t] + bias[R]
// ============================================================================
__global__ void __launch_bounds__(256, 2) xproj_kernel(
    const float* __restrict__ bg, const float* __restrict__ bi,
    const float* __restrict__ bf, const float* __restrict__ bo) {
    extern __shared__ uint32_t sm[];
    const uint32_t smem0 = (uint32_t)__cvta_generic_to_shared(sm);
    const int tid = threadIdx.x;
    const int m_base = blockIdx.x * 128;
    const int mt0 = m_base >> 4;
    const int t = blockIdx.y;
    const int warp = tid >> 5, lane = tid & 31;
    const int wm = warp & 1, wn = warp >> 1;
    const int gid = lane >> 2, tig = lane & 3;

    float acc[4][4][4];
#pragma unroll
    for (int a = 0; a < 4; ++a)
#pragma unroll
        for (int b = 0; b < 4; ++b) {
            acc[a][b][0] = acc[a][b][1] = acc[a][b][2] = acc[a][b][3] = 0.f;
        }

    auto issue = [&](int kc, int buf) {
#pragma unroll
        for (int c = 0; c < 4; ++c) {                       // A: 4096 u32
            int u = c * 256 + tid;
            int idx = u >> 5, lq = u & 31;
            int k16l = idx >> 3, mtl = idx & 7;
            const uint32_t* src = g_WXh + ((size_t)(mt0 + mtl) * 32 + kc * 4 + k16l) * 128 + lq * 4;
            cp16(smem0 + (uint32_t)(buf * 4096 + idx * 128 + lq * 4) * 4, src);
        }
#pragma unroll
        for (int c = 0; c < 4; ++c) {                       // B: 4096 u32
            int u = c * 256 + tid;
            int idx = u >> 4, q16 = u & 15;
            const uint32_t* src = g_XTh + ((size_t)(t * 32 + kc * 4) * 16 + idx) * 64 + q16 * 4;
            cp16(smem0 + (uint32_t)(8192 + buf * 4096 + idx * 64 + q16 * 4) * 4, src);
        }
    };
    issue(0, 0); cpcommit();
    issue(1, 1); cpcommit();

#pragma unroll 1
    for (int kc = 0; kc < 8; ++kc) {
        if (kc < 7) cpwait<1>(); else cpwait<0>();
        __syncthreads();
        const uint32_t* A = sm + (kc & 1) * 4096;
        const uint32_t* B = sm + 8192 + (kc & 1) * 4096;
#pragma unroll
        for (int k16l = 0; k16l < 4; ++k16l) {
            uint4 af[4];
#pragma unroll
            for (int mf = 0; mf < 4; ++mf)
                af[mf] = *(const uint4*)(A + ((k16l * 8 + wm * 4 + mf) * 32 + lane) * 4);
#pragma unroll
            for (int nf = 0; nf < 4; ++nf) {
                int n8 = wn * 4 + nf;
                uint2 b01 = *(const uint2*)(B + (k16l * 16 + n8) * 64 + lane * 2);
#pragma unroll
                for (int mf = 0; mf < 4; ++mf)
                    mma16(acc[mf][nf], af[mf].x, af[mf].y, af[mf].z, af[mf].w, b01.x, b01.y);
            }
        }
        __syncthreads();
        if (kc + 2 < 8) { issue(kc + 2, kc & 1); cpcommit(); }
    }

#pragma unroll
    for (int mf = 0; mf < 4; ++mf) {
        int R0 = m_base + wm * 64 + mf * 16 + gid;
        int R1 = R0 + 8;
        float bv0 = sel4(bg, bi, bf, bo, R0 >> 10)[R0 & 1023];
        float bv1 = sel4(bg, bi, bf, bo, R1 >> 10)[R1 & 1023];
#pragma unroll
        for (int nf = 0; nf < 4; ++nf) {
            int cc = wn * 32 + nf * 8 + tig * 2;
            float2 v0 = { acc[mf][nf][0] + bv0, acc[mf][nf][1] + bv0 };
            float2 v1 = { acc[mf][nf][2] + bv1, acc[mf][nf][3] + bv1 };
            *(float2*)&g_XS[((size_t)t * G4H + R0) * BATCH + cc] = v0;
            *(float2*)&g_XS[((size_t)t * G4H + R1) * BATCH + cc] = v1;
        }
    }
}

// ============================================================================
// lstm v10: v7 base (flag-array barrier, warp-private pipelines) with a
// DEEP 8-buffer ring, 7 chunks in flight; next chunk issued immediately
// after cpwait, before the mma consume (earliest legal LSU issue point).
// M=32 (4 gates x 8 units) x N=128 x K=1024, fp16 m16n8k16.
// smem: sW 65536 B + sB 8 x 8192 B = 131072 B.
// ============================================================================
#define SB_OFF   16384                  // u32 offset of sB

__global__ void __launch_bounds__(LT, 1) lstm_kernel(
    const float* __restrict__ c0,
    const float* __restrict__ Wg, const float* __restrict__ Wi,
    const float* __restrict__ Wf, const float* __restrict__ Wo,
    float* __restrict__ out) {
    extern __shared__ uint32_t sm[];
    uint32_t* sW  = sm;                          // 16384 u32 (fp16 A frags)
    const uint32_t smem0 = (uint32_t)__cvta_generic_to_shared(sm);
    const int tid = threadIdx.x;
    const int j0 = blockIdx.x * 8;
    const int warp = tid >> 5, lane = tid & 31;
    const int gid = lane >> 2, tig = lane & 3;
    const int hreg = (j0 >> 3) & 1;
    const int hk16 = j0 >> 4;

    // prologue: Wh -> fp16 A-frag-permuted smem (16384 u32)
#pragma unroll 1
    for (int i = 0; i < 128; ++i) {
        int o    = i * LT + tid;
        int q    = o & 3, ln = (o >> 2) & 31, mt = (o >> 7) & 1, k16 = o >> 8;
        int row  = mt * 16 + (ln >> 2) + (q & 1) * 8;
        int kk   = k16 * 16 + (ln & 3) * 2 + (q >> 1) * 8;
        const float* W = sel4(Wg, Wi, Wf, Wo, row >> 3);
        const float* wr = W + (size_t)(j0 + (row & 7)) * HID + kk;
        sW[o] = h2pack(wr[0], wr[1]);
    }
    // c state in acc layout: creg[nf*2+c] = c(u=gid, n=warp*32+nf*8+tig*2+c)
    float creg[8];
#pragma unroll
    for (int nf = 0; nf < 4; ++nf)
#pragma unroll
        for (int c = 0; c < 2; ++c)
            creg[nf * 2 + c] = c0[(j0 + gid) * BATCH + warp * 32 + nf * 8 + tig * 2 + c];
    __syncthreads();

#pragma unroll 1
    for (int t = 0; t < TSTEPS; ++t) {
        // XS prefetch into registers (independent of barrier -> hides latency)
        float xsv[4][8];
        {
            const size_t xb = (size_t)t * (G4H * BATCH);
            const int nb = warp * 32 + tig * 2;
#pragma unroll
            for (int g = 0; g < 4; ++g) {
                const float* p = &g_XS[xb + (size_t)((g << 10) + j0 + gid) * BATCH + nb];
#pragma unroll
                for (int nf = 0; nf < 4; ++nf) {
                    xsv[g][nf * 2]     = p[nf * 8];
                    xsv[g][nf * 2 + 1] = p[nf * 8 + 1];
                }
            }
        }
        // grid barrier: wait until all blocks finished step t-1
        if (t > 0 && warp == 0) {
            const unsigned tgt = (unsigned)t;
            const volatile unsigned* f = (const volatile unsigned*)g_flags;
            for (;;) {
                unsigned v0 = f[lane], v1 = f[lane + 32], v2 = f[lane + 64], v3 = f[lane + 96];
                bool ok = (v0 >= tgt) && (v1 >= tgt) && (v2 >= tgt) && (v3 >= tgt);
                if (__all_sync(0xffffffffu, ok)) break;
                __nanosleep(32);
            }
            __threadfence();
        }
        __syncthreads();                                  // sync #1

        const uint32_t* hin = g_Hp[(t + 1) & 1];
        // warp-private B pipeline: chunk = 2 k16, this warp's n8 quarter = 512 u32
        auto issueB = [&](int c, int buf) {
#pragma unroll
            for (int i = 0; i < 4; ++i) {
                int rl = i * 2 + (lane >> 4);             // 0..7 = k16l*4 + r
                int col = (lane & 15) * 4;
                int k16l = rl >> 2, r = rl & 3;
                int rowg = (c * 2 + k16l) * 16 + warp * 4 + r;
                int rows = (k16l * 16 + warp * 4 + r);
                cp16(smem0 + (uint32_t)(SB_OFF + buf * 2048 + rows * 64 + col) * 4,
                     hin + (size_t)rowg * 64 + col);
            }
            cpcommit();
        };
#pragma unroll
        for (int c = 0; c < 7; ++c) issueB(c, c);        // 7 chunks in flight

        float acc[2][4][4];
#pragma unroll
        for (int mt = 0; mt < 2; ++mt)
#pragma unroll
            for (int nf = 0; nf < 4; ++nf) {
                acc[mt][nf][0] = acc[mt][nf][1] = acc[mt][nf][2] = acc[mt][nf][3] = 0.f;
            }
#pragma unroll 1
        for (int kc = 0; kc < 32; ++kc) {
            cpwait<6>();                                  // warp-local wait, chunk kc ready
            if (kc + 7 < 32) issueB(kc + 7, (kc + 7) & 7);
            else cpcommit();                              // keep group count exact
            const uint32_t* B = sm + SB_OFF + (kc & 7) * 2048;
#pragma unroll
            for (int k16l = 0; k16l < 2; ++k16l) {
                const int k16 = kc * 2 + k16l;
                uint4 a0 = *(const uint4*)(sW + ((k16 * 2) * 32 + lane) * 4);
                uint4 a1 = *(const uint4*)(sW + ((k16 * 2 + 1) * 32 + lane) * 4);
#pragma unroll
                for (int nf = 0; nf < 4; ++nf) {
                    const int n8 = warp * 4 + nf;
                    uint2 b01 = *(const uint2*)(B + (k16l * 16 + n8) * 64 + lane * 2);
                    mma16(acc[0][nf], a0.x, a0.y, a0.z, a0.w, b01.x, b01.y);
                    mma16(acc[1][nf], a1.x, a1.y, a1.z, a1.w, b01.x, b01.y);
                }
            }
        }
        // register epilogue + direct h frag write
        {
            float hv[8];
#pragma unroll
            for (int nf = 0; nf < 4; ++nf)
#pragma unroll
                for (int c = 0; c < 2; ++c) {
                    int e = nf * 2 + c;
                    float zg = acc[0][nf][c]     + xsv[0][e];
                    float zi = acc[0][nf][2 + c] + xsv[1][e];
                    float zf = acc[1][nf][c]     + xsv[2][e];
                    float zo = acc[1][nf][2 + c] + xsv[3][e];
                    float cv = tanhf(zg) * sigm(zi) + creg[e] * sigm(zf);
                    creg[e] = cv;
                    hv[e] = tanhf(cv) * sigm(zo);
                }
            uint32_t* hw = g_Hp[t & 1];
            const int p2 = gid >> 1;
            const bool even = (gid & 1) == 0;
#pragma unroll
            for (int nf = 0; nf < 4; ++nf)
#pragma unroll
                for (int c = 0; c < 2; ++c) {
                    int e = nf * 2 + c;
                    float partner = __shfl_xor_sync(0xffffffffu, hv[e], 4);
                    if (even) {
                        uint32_t v = h2pack(hv[e], partner);
                        hw[(hk16 * 16 + warp * 4 + nf) * 64 +
                           ((tig * 2 + c) * 4 + p2) * 2 + hreg] = v;
                    }
                }
            if (t == TSTEPS - 1) {
#pragma unroll
                for (int nf = 0; nf < 4; ++nf)
#pragma unroll
                    for (int c = 0; c < 2; ++c)
                        out[(j0 + gid) * BATCH + warp * 32 + nf * 8 + tig * 2 + c] = hv[nf * 2 + c];
            }
        }
        __threadfence();                                  // each thread releases its h writes
        __syncthreads();                                  // sync #2
        if (tid == 0) *(volatile unsigned*)&g_flags[blockIdx.x] = (unsigned)(t + 1);
    }
}

// ============================================================================
extern "C" void kernel_launch(void* const* d_in, const int* in_sizes, int n_in,
                              void* d_out, int out_size) {
    const float* x   = (const float*)d_in[0];
    const float* c0  = (const float*)d_in[1];
    const float* h0  = (const float*)d_in[2];
    const float* Wgx = (const float*)d_in[3];
    const float* Wix = (const float*)d_in[4];
    const float* Wfx = (const float*)d_in[5];
    const float* Wox = (const float*)d_in[6];
    const float* Wgh = (const float*)d_in[7];
    const float* Wih = (const float*)d_in[8];
    const float* Wfh = (const float*)d_in[9];
    const float* Woh = (const float*)d_in[10];
    const float* bg  = (const float*)d_in[11];
    const float* bi  = (const float*)d_in[12];
    const float* bf  = (const float*)d_in[13];
    const float* bo  = (const float*)d_in[14];
    float* out = (float*)d_out;

    cudaFuncSetAttribute(xproj_kernel, cudaFuncAttributeMaxDynamicSharedMemorySize, 65536);
    cudaFuncSetAttribute(lstm_kernel,  cudaFuncAttributeMaxDynamicSharedMemorySize, 131072);

    prep_w_kernel<<<1024, 256>>>(Wgx, Wix, Wfx, Wox);
    prep_h0_kernel<<<256, 256>>>(h0);
    prep_xt_kernel<<<8192, 256>>>(x);
    xproj_kernel<<<dim3(32, 256), 256, 65536>>>(bg, bi, bf, bo);
    lstm_kernel<<<NB, LT, 131072>>>(c0, Wgh, Wih, Wfh, Woh, out);
}